// round 1
// baseline (speedup 1.0000x reference)
#include <cuda_runtime.h>

// Problem constants (target: [B, T, L] float32)
constexpr int B_ = 32;
constexpr int T_ = 8;
constexpr int L_ = 256;
constexpr int TILE = 128;   // output quadrant per block

// source[b, l1, l2] = (1/(T*L)) * sum_t sum_n x[n] * x[n-l1] * x[n-l2]
// with x[k] = 0 for k < 0 (zero left padding).
//
// Grid: (4, 32) — blockIdx.x selects the 128x128 quadrant, blockIdx.y = batch.
// Block: 256 threads, each owning an 8x8 register tile in a STRIDED layout
// (l = base + lane + 16*r) so shared loads are bank-conflict free.
__global__ __launch_bounds__(256, 1)
void bispectrum_kernel(const float* __restrict__ tgt, float* __restrict__ out)
{
    __shared__ float xs[2 * L_];   // [0..255] = 0 pad, [256..511] = x[t]

    const int b  = blockIdx.y;
    const int q  = blockIdx.x;
    const int l1_base = (q >> 1) * TILE;
    const int l2_base = (q & 1)  * TILE;

    const int tid = threadIdx.x;
    const int tx  = tid & 15;   // 16 lanes -> l2 strided
    const int ty  = tid >> 4;   // 16 rows  -> l1 strided

    float acc[8][8];
#pragma unroll
    for (int i = 0; i < 8; i++)
#pragma unroll
        for (int j = 0; j < 8; j++) acc[i][j] = 0.0f;

    // Base offsets: xa[i] = xs[ba0 + n - 16*i], xb[j] = xs[bb0 + n - 16*j]
    const int ba0 = L_ - l1_base - ty;
    const int bb0 = L_ - l2_base - tx;

    for (int t = 0; t < T_; t++) {
        __syncthreads();
        xs[tid]       = 0.0f;
        xs[L_ + tid]  = tgt[(b * T_ + t) * L_ + tid];
        __syncthreads();

#pragma unroll 2
        for (int n = 0; n < L_; n++) {
            const float xn = xs[L_ + n];

            float xa[8], xb[8], p[8];
#pragma unroll
            for (int i = 0; i < 8; i++) xa[i] = xs[ba0 + n - 16 * i];
#pragma unroll
            for (int j = 0; j < 8; j++) xb[j] = xs[bb0 + n - 16 * j];
#pragma unroll
            for (int i = 0; i < 8; i++) p[i] = xn * xa[i];

#pragma unroll
            for (int i = 0; i < 8; i++)
#pragma unroll
                for (int j = 0; j < 8; j++)
                    acc[i][j] = fmaf(p[i], xb[j], acc[i][j]);
        }
    }

    const float scale = 1.0f / (float)(T_ * L_);
    float* ob = out + (size_t)b * L_ * L_;
#pragma unroll
    for (int i = 0; i < 8; i++) {
        const int l1 = l1_base + ty + 16 * i;
#pragma unroll
        for (int j = 0; j < 8; j++) {
            const int l2 = l2_base + tx + 16 * j;
            ob[l1 * L_ + l2] = acc[i][j] * scale;
        }
    }
}

extern "C" void kernel_launch(void* const* d_in, const int* in_sizes, int n_in,
                              void* d_out, int out_size)
{
    const float* tgt = (const float*)d_in[0];
    float* out = (float*)d_out;

    dim3 grid(4, B_);
    bispectrum_kernel<<<grid, 256>>>(tgt, out);

    // Reference returns (source, target): echo target after source if the
    // output buffer holds both.
    const long long src_elems = (long long)B_ * L_ * L_;        // 2,097,152
    const long long tgt_elems = (long long)B_ * T_ * L_;        // 65,536
    if ((long long)out_size >= src_elems + tgt_elems) {
        cudaMemcpyAsync(out + src_elems, tgt, sizeof(float) * tgt_elems,
                        cudaMemcpyDeviceToDevice);
    }
}